// round 15
// baseline (speedup 1.0000x reference)
#include <cuda_runtime.h>
#include <cstdint>
#include <math.h>

// ---------------- problem constants ----------------
#define TOK   4096
#define RNUM  8
#define DDIM  768
#define FDIM  3072
#define VDIM  2048

// ---------------- device scratch ----------------
__device__ __align__(256) float g_Aperm[(size_t)TOK * DDIM];   // gathered + tf32-rounded activations
__device__ __align__(256) float g_H[(size_t)TOK * FDIM];       // relu(x@W1+b1), permuted, tf32-rounded
__device__ __align__(256) float g_logits[(size_t)TOK * VDIM];  // h@W2+b2, permuted rows
__device__ int g_perm[TOK];
__device__ int g_seg_start[RNUM + 1];

// ---------------- helpers ----------------
__device__ __forceinline__ uint32_t smem_u32(const void* p) {
    return (uint32_t)__cvta_generic_to_shared(p);
}
__device__ __forceinline__ void cp16(uint32_t s, const void* g) {
    asm volatile("cp.async.cg.shared.global [%0], [%1], 16;\n" :: "r"(s), "l"(g));
}
__device__ __forceinline__ uint32_t f2tf32(float x) {
    uint32_t o;
    asm("cvt.rna.tf32.f32 %0, %1;\n" : "=r"(o) : "f"(x));
    return o;
}
__device__ __forceinline__ float round_tf32(float x) {
    return __uint_as_float(f2tf32(x));
}
__device__ __forceinline__ void ldsm4(uint32_t* r, uint32_t addr) {
    asm volatile("ldmatrix.sync.aligned.m8n8.x4.shared.b16 {%0,%1,%2,%3}, [%4];\n"
                 : "=r"(r[0]), "=r"(r[1]), "=r"(r[2]), "=r"(r[3]) : "r"(addr));
}
__device__ __forceinline__ void mma_tf32(float* c, const uint32_t* a, const uint32_t* b) {
    asm volatile(
        "mma.sync.aligned.m16n8k8.row.col.f32.tf32.tf32.f32 "
        "{%0,%1,%2,%3},{%4,%5,%6,%7},{%8,%9},{%0,%1,%2,%3};\n"
        : "+f"(c[0]), "+f"(c[1]), "+f"(c[2]), "+f"(c[3])
        : "r"(a[0]), "r"(a[1]), "r"(a[2]), "r"(a[3]), "r"(b[0]), "r"(b[1]));
}

// ---------------- kernel 1: bucket tokens by route ----------------
__global__ void bucket_kernel(const int* __restrict__ route_ids) {
    __shared__ int s_cnt[RNUM];
    __shared__ int s_cur[RNUM];
    const int t = threadIdx.x;
    if (t < RNUM) s_cnt[t] = 0;
    __syncthreads();
    for (int i = t; i < TOK; i += blockDim.x)
        atomicAdd(&s_cnt[route_ids[i]], 1);
    __syncthreads();
    if (t == 0) {
        int off = 0;
        for (int r = 0; r < RNUM; r++) {
            g_seg_start[r] = off;
            s_cur[r] = off;
            off += s_cnt[r];
        }
        g_seg_start[RNUM] = off;
    }
    __syncthreads();
    for (int i = t; i < TOK; i += blockDim.x) {
        int r = route_ids[i];
        int pos = atomicAdd(&s_cur[r], 1);
        g_perm[pos] = i;
    }
}

// ---------------- kernel 2: gather A rows by perm, round to tf32 ----------------
__global__ __launch_bounds__(192)
void gather_kernel(const float* __restrict__ e_two) {
    const int row = blockIdx.x;
    const int tok = g_perm[row];
    const float4* src = reinterpret_cast<const float4*>(e_two + (size_t)tok * DDIM);
    float4* dst = reinterpret_cast<float4*>(g_Aperm + (size_t)row * DDIM);
    float4 v = src[threadIdx.x];
    v.x = round_tf32(v.x); v.y = round_tf32(v.y);
    v.z = round_tf32(v.z); v.w = round_tf32(v.w);
    dst[threadIdx.x] = v;
}

// ---------------- tf32 GEMM: dual-ldmatrix with in-kernel B transpose ----------------
// R13-proven structure (446us): BK=32, 3-stage A cp.async, 2-stage B via
// per-thread column LDG -> cvt -> STS, dual ldmatrix fragments, 4 warps of
// 64x64, 2 CTAs/SM. Delta vs R13: staging spread FINER across the ks gaps —
// g0=loadA, g1=stsB.lo, g2=stsB.hi, g3=ldgB (issue-only LDGs fly over the
// barrier; >=600cyc before first consumption, >= DRAM latency).
static constexpr int BK = 32;
static constexpr int TSTRIDE = 36;                       // 32 + 4 pad floats
static constexpr int TILE_FLOATS = 128 * TSTRIDE;        // 4608 floats per tile
static constexpr int ASTAGES = 3;
static constexpr int SMEM_BYTES = (ASTAGES + 2) * TILE_FLOATS * 4;   // 92,160 B

template <int KTOT, int NTOT, bool RELU>
__global__ void __launch_bounds__(128, 2)
gemm_dlt(const float* __restrict__ Abase,
         const float* __restrict__ Bbase,
         const float* __restrict__ biasBase,
         float* __restrict__ Cbase) {
    constexpr int NK = KTOT / BK;

    extern __shared__ float smem[];
    float* sA  = smem;                         // [3][128][36]
    float* sBt = smem + ASTAGES * TILE_FLOATS; // [2][128][36]  (row = n, col = k)

    const int r    = blockIdx.z;
    const int seg0 = g_seg_start[r];
    const int cnt  = g_seg_start[r + 1] - seg0;
    const int m0   = blockIdx.y * 128;
    if (m0 >= cnt) return;
    const int n0 = blockIdx.x * 128;

    const float* B    = Bbase + (size_t)r * (size_t)KTOT * NTOT;
    const float* bias = biasBase + (size_t)r * NTOT;

    const int tid  = threadIdx.x;
    const int warp = tid >> 5;
    const int lane = tid & 31;
    const int wm = warp & 1;    // 2 warp-rows of 64
    const int wn = warp >> 1;   // 2 warp-cols of 64
    const int lg = lane >> 2;
    const int lt = lane & 3;

    // ---- A loader: 128x32 floats = 1024 16B chunks, 8 per thread, cp.async ----
    auto loadA = [&](int kt, int buf) {
        const int k0 = kt * BK;
        float* dA = sA + buf * TILE_FLOATS;
        #pragma unroll
        for (int i = 0; i < 8; i++) {
            int idx = tid + i * 128;
            int row = idx >> 3;
            int ch  = idx & 7;
            int grow = seg0 + m0 + row;
            if (grow > TOK - 1) grow = TOK - 1;     // clamp; stores guarded
            cp16(smem_u32(dA + row * TSTRIDE + ch * 4),
                 Abase + (size_t)grow * KTOT + k0 + ch * 4);
        }
        asm volatile("cp.async.commit_group;\n");
    };

    // ---- B staging: thread tid owns column n = n0+tid of the B tile ----
    const float* bCol = B + n0 + tid;            // + k*NTOT indexes rows
    float rawB[BK];                              // raw fp32 column for tile kt
    auto ldgB = [&](int kt) {                    // all 32 LDGs, issue-only
        const int k0 = kt * BK;
        #pragma unroll
        for (int j = 0; j < BK; j++)
            rawB[j] = __ldg(bCol + (size_t)(k0 + j) * NTOT);
    };
    auto stsB_half = [&](int buf, int half) {    // round + store 16 floats of row n=tid
        float* dst = sBt + buf * TILE_FLOATS + tid * TSTRIDE + half * 16;
        #pragma unroll
        for (int j = 0; j < 16; j += 4) {
            const int jj = half * 16 + j;
            float4 v;
            v.x = round_tf32(rawB[jj + 0]);
            v.y = round_tf32(rawB[jj + 1]);
            v.z = round_tf32(rawB[jj + 2]);
            v.w = round_tf32(rawB[jj + 3]);
            *reinterpret_cast<float4*>(dst + j) = v;
        }
    };

    float acc[4][8][4];
    #pragma unroll
    for (int mt = 0; mt < 4; mt++)
        #pragma unroll
        for (int nt = 0; nt < 8; nt++)
            #pragma unroll
            for (int j = 0; j < 4; j++) acc[mt][nt][j] = 0.f;

    // ldmatrix lane addresses (bytes within a tile buffer) — proven mappings
    const int a_row = wm * 64 + (lane & 7) + (((lane >> 3) & 1) << 3);
    const int a_colb = (((lane >> 4) & 1) << 4);
    const uint32_t aBase = smem_u32(sA) + (uint32_t)(a_row * TSTRIDE * 4 + a_colb);
    const int b_row = wn * 64 + (lane & 7) + (((lane >> 4) & 1) << 3);
    const int b_colb = (((lane >> 3) & 1) << 4);
    const uint32_t bBase = smem_u32(sBt) + (uint32_t)(b_row * TSTRIDE * 4 + b_colb);

    // one ks step of fragment loads + MMAs (R10/R13 verbatim)
    auto do_ks = [&](uint32_t aBuf, uint32_t bBuf, int ks) {
        uint32_t afr[4][4];
        #pragma unroll
        for (int mt = 0; mt < 4; mt++)
            ldsm4(afr[mt], aBuf + mt * (16 * TSTRIDE * 4) + ks * 32);

        uint32_t bfr[8][2];
        #pragma unroll
        for (int ntp = 0; ntp < 4; ntp++) {
            uint32_t q[4];
            ldsm4(q, bBuf + ntp * (16 * TSTRIDE * 4) + ks * 32);
            bfr[2 * ntp + 0][0] = q[0];
            bfr[2 * ntp + 0][1] = q[1];
            bfr[2 * ntp + 1][0] = q[2];
            bfr[2 * ntp + 1][1] = q[3];
        }
        #pragma unroll
        for (int mt = 0; mt < 4; mt++)
            #pragma unroll
            for (int nt = 0; nt < 8; nt++)
                mma_tf32(acc[mt][nt], afr[mt], bfr[nt]);
    };

    // ---- prologue ----
    loadA(0, 0);                 // group: A0
    loadA(1, 1);                 // group: A1
    ldgB(0);
    stsB_half(0, 0);
    stsB_half(0, 1);             // sBt[0] = B(0); no readers yet
    if (NK > 1) ldgB(1);         // rawB = B(1)

    for (int kt = 0; kt < NK; kt++) {
        const int abuf = kt % ASTAGES;
        const int bbuf = kt & 1;
        // A(kt) complete for this thread (pending = {kt, kt+1} before wait)
        asm volatile("cp.async.wait_group 1;\n");
        // ...for all threads; STS of sBt[bbuf] visible; stage buffers from kt-1 free
        __syncthreads();

        const uint32_t aBuf = aBase + abuf * (TILE_FLOATS * 4);
        const uint32_t bBuf = bBase + bbuf * (TILE_FLOATS * 4);
        const bool more  = kt + 1 < NK;
        const bool more2 = kt + 2 < NK;

        // staging spread one small op per ks gap; tensor pipe never waits
        do_ks(aBuf, bBuf, 0);
        if (more2) loadA(kt + 2, (kt + 2) % ASTAGES);    // g0: commit A(kt+2)
        else       asm volatile("cp.async.commit_group;\n");  // keep accounting exact
        do_ks(aBuf, bBuf, 1);
        if (more) stsB_half(bbuf ^ 1, 0);                // g1: B(kt+1) lo -> smem
        do_ks(aBuf, bBuf, 2);
        if (more) stsB_half(bbuf ^ 1, 1);                // g2: B(kt+1) hi -> smem
        do_ks(aBuf, bBuf, 3);
        if (more2) ldgB(kt + 2);                         // g3: rawB = B(kt+2), flies
    }                                                    //     over barrier (~600cyc)

    __syncthreads();

    // epilogue: bias (+relu+tf32-round for phase1), guarded float2 stores
    #pragma unroll
    for (int mt = 0; mt < 4; mt++) {
        #pragma unroll
        for (int half = 0; half < 2; half++) {
            const int rowl = wm * 64 + mt * 16 + lg + half * 8;
            const int mrow = m0 + rowl;
            if (mrow < cnt) {
                float* crow = Cbase + (size_t)(seg0 + mrow) * NTOT;
                #pragma unroll
                for (int nt = 0; nt < 8; nt++) {
                    const int col = n0 + wn * 64 + nt * 8 + lt * 2;
                    float v0 = acc[mt][nt][half * 2 + 0] + bias[col];
                    float v1 = acc[mt][nt][half * 2 + 1] + bias[col + 1];
                    if (RELU) {
                        v0 = round_tf32(fmaxf(v0, 0.f));
                        v1 = round_tf32(fmaxf(v1, 0.f));
                    }
                    *reinterpret_cast<float2*>(crow + col) = make_float2(v0, v1);
                }
            }
        }
    }
}

// ---------------- softmax + scatter: 512 threads, float4, fast exp ----------------
__global__ __launch_bounds__(512)
void softmax_kernel(float* __restrict__ out) {
    const int i   = blockIdx.x;
    const int tok = g_perm[i];
    const float4* lrow = reinterpret_cast<const float4*>(g_logits + (size_t)i * VDIM);
    float4*       orow = reinterpret_cast<float4*>(out + (size_t)tok * VDIM);
    const int tid = threadIdx.x;

    float4 v = lrow[tid];               // 512 threads x 4 = 2048
    float mx = fmaxf(fmaxf(v.x, v.y), fmaxf(v.z, v.w));
    #pragma unroll
    for (int o = 16; o; o >>= 1) mx = fmaxf(mx, __shfl_xor_sync(0xffffffffu, mx, o));

    __shared__ float sred[16];
    const int w = tid >> 5;
    if ((tid & 31) == 0) sred[w] = mx;
    __syncthreads();
    float bmx = sred[0];
    #pragma unroll
    for (int j = 1; j < 16; j++) bmx = fmaxf(bmx, sred[j]);

    v.x = __expf(v.x - bmx);
    v.y = __expf(v.y - bmx);
    v.z = __expf(v.z - bmx);
    v.w = __expf(v.w - bmx);
    float s = (v.x + v.y) + (v.z + v.w);
    #pragma unroll
    for (int o = 16; o; o >>= 1) s += __shfl_xor_sync(0xffffffffu, s, o);
    __syncthreads();
    if ((tid & 31) == 0) sred[w] = s;
    __syncthreads();
    float tot = 0.f;
    #pragma unroll
    for (int j = 0; j < 16; j++) tot += sred[j];
    const float inv = 1.f / tot;
    v.x *= inv; v.y *= inv; v.z *= inv; v.w *= inv;
    orow[tid] = v;
}

// ---------------- launch ----------------
extern "C" void kernel_launch(void* const* d_in, const int* in_sizes, int n_in,
                              void* d_out, int out_size) {
    const float* e_two     = (const float*)d_in[0];   // [4,1024,768]
    const int*   route_ids = (const int*)d_in[1];     // [4,1024]
    const float* W1        = (const float*)d_in[2];   // [8,768,3072]
    const float* b1        = (const float*)d_in[3];   // [8,3072]
    const float* W2        = (const float*)d_in[4];   // [8,3072,2048]
    const float* b2        = (const float*)d_in[5];   // [8,2048]
    float*       out       = (float*)d_out;           // [4,1024,2048]

    void *pA, *pH, *pL;
    cudaGetSymbolAddress(&pA, g_Aperm);
    cudaGetSymbolAddress(&pH, g_H);
    cudaGetSymbolAddress(&pL, g_logits);

    static bool attr_done = false;
    if (!attr_done) {
        cudaFuncSetAttribute(gemm_dlt<DDIM, FDIM, true>,
                             cudaFuncAttributeMaxDynamicSharedMemorySize, SMEM_BYTES);
        cudaFuncSetAttribute(gemm_dlt<FDIM, VDIM, false>,
                             cudaFuncAttributeMaxDynamicSharedMemorySize, SMEM_BYTES);
        attr_done = true;
    }

    bucket_kernel<<<1, 1024>>>(route_ids);
    gather_kernel<<<TOK, 192>>>(e_two);

    dim3 g1(FDIM / 128, TOK / 128, RNUM);   // (24, 32, 8)
    gemm_dlt<DDIM, FDIM, true><<<g1, 128, SMEM_BYTES>>>(
        (const float*)pA, W1, b1, (float*)pH);

    dim3 g2(VDIM / 128, TOK / 128, RNUM);   // (16, 32, 8)
    gemm_dlt<FDIM, VDIM, false><<<g2, 128, SMEM_BYTES>>>(
        (const float*)pH, W2, b2, (float*)pL);

    softmax_kernel<<<TOK, 512>>>(out);
}

// round 16
// speedup vs baseline: 1.0653x; 1.0653x over previous
#include <cuda_runtime.h>
#include <cstdint>
#include <math.h>

// ---------------- problem constants ----------------
#define TOK   4096
#define RNUM  8
#define DDIM  768
#define FDIM  3072
#define VDIM  2048

// ---------------- device scratch ----------------
__device__ __align__(256) float g_Aperm[(size_t)TOK * DDIM];   // gathered + tf32-rounded activations
__device__ __align__(256) float g_H[(size_t)TOK * FDIM];       // relu(x@W1+b1), permuted, tf32-rounded
__device__ __align__(256) float g_logits[(size_t)TOK * VDIM];  // h@W2+b2, permuted rows
__device__ int g_perm[TOK];
__device__ int g_seg_start[RNUM + 1];

// ---------------- helpers ----------------
__device__ __forceinline__ uint32_t smem_u32(const void* p) {
    return (uint32_t)__cvta_generic_to_shared(p);
}
__device__ __forceinline__ void cp16(uint32_t s, const void* g) {
    asm volatile("cp.async.cg.shared.global [%0], [%1], 16;\n" :: "r"(s), "l"(g));
}
__device__ __forceinline__ uint32_t f2tf32(float x) {
    uint32_t o;
    asm("cvt.rna.tf32.f32 %0, %1;\n" : "=r"(o) : "f"(x));
    return o;
}
__device__ __forceinline__ float round_tf32(float x) {
    return __uint_as_float(f2tf32(x));
}
__device__ __forceinline__ void ldsm4(uint32_t* r, uint32_t addr) {
    asm volatile("ldmatrix.sync.aligned.m8n8.x4.shared.b16 {%0,%1,%2,%3}, [%4];\n"
                 : "=r"(r[0]), "=r"(r[1]), "=r"(r[2]), "=r"(r[3]) : "r"(addr));
}
__device__ __forceinline__ void mma_tf32(float* c, const uint32_t* a, const uint32_t* b) {
    asm volatile(
        "mma.sync.aligned.m16n8k8.row.col.f32.tf32.tf32.f32 "
        "{%0,%1,%2,%3},{%4,%5,%6,%7},{%8,%9},{%0,%1,%2,%3};\n"
        : "+f"(c[0]), "+f"(c[1]), "+f"(c[2]), "+f"(c[3])
        : "r"(a[0]), "r"(a[1]), "r"(a[2]), "r"(a[3]), "r"(b[0]), "r"(b[1]));
}

// ---------------- kernel 1: bucket tokens by route ----------------
__global__ void bucket_kernel(const int* __restrict__ route_ids) {
    __shared__ int s_cnt[RNUM];
    __shared__ int s_cur[RNUM];
    const int t = threadIdx.x;
    if (t < RNUM) s_cnt[t] = 0;
    __syncthreads();
    for (int i = t; i < TOK; i += blockDim.x)
        atomicAdd(&s_cnt[route_ids[i]], 1);
    __syncthreads();
    if (t == 0) {
        int off = 0;
        for (int r = 0; r < RNUM; r++) {
            g_seg_start[r] = off;
            s_cur[r] = off;
            off += s_cnt[r];
        }
        g_seg_start[RNUM] = off;
    }
    __syncthreads();
    for (int i = t; i < TOK; i += blockDim.x) {
        int r = route_ids[i];
        int pos = atomicAdd(&s_cur[r], 1);
        g_perm[pos] = i;
    }
}

// ---------------- kernel 2: gather A rows by perm, round to tf32 ----------------
__global__ __launch_bounds__(192)
void gather_kernel(const float* __restrict__ e_two) {
    const int row = blockIdx.x;
    const int tok = g_perm[row];
    const float4* src = reinterpret_cast<const float4*>(e_two + (size_t)tok * DDIM);
    float4* dst = reinterpret_cast<float4*>(g_Aperm + (size_t)row * DDIM);
    float4 v = src[threadIdx.x];
    v.x = round_tf32(v.x); v.y = round_tf32(v.y);
    v.z = round_tf32(v.z); v.w = round_tf32(v.w);
    dst[threadIdx.x] = v;
}

// ---------------- tf32 GEMM: dual-ldmatrix with in-kernel B transpose ----------------
// R13-proven loop (446us), byte-for-byte: BK=32, 3-stage A cp.async, 2-stage B
// via column LDG -> cvt -> STS, dual ldmatrix fragments, 4 warps of 64x64,
// 2 CTAs/SM, staging g0=loadA / g1=stsB / g2=ldgB in the ks gaps.
// Delta vs R13: blockIdx roles transposed — x = m-tile (fastest), y = n-tile —
// so co-scheduled CTAs share the same B n-slice (B stream becomes L2-resident).
static constexpr int BK = 32;
static constexpr int TSTRIDE = 36;                       // 32 + 4 pad floats
static constexpr int TILE_FLOATS = 128 * TSTRIDE;        // 4608 floats per tile
static constexpr int ASTAGES = 3;
static constexpr int SMEM_BYTES = (ASTAGES + 2) * TILE_FLOATS * 4;   // 92,160 B

template <int KTOT, int NTOT, bool RELU>
__global__ void __launch_bounds__(128, 2)
gemm_dlt(const float* __restrict__ Abase,
         const float* __restrict__ Bbase,
         const float* __restrict__ biasBase,
         float* __restrict__ Cbase) {
    constexpr int NK = KTOT / BK;

    extern __shared__ float smem[];
    float* sA  = smem;                         // [3][128][36]
    float* sBt = smem + ASTAGES * TILE_FLOATS; // [2][128][36]  (row = n, col = k)

    const int r    = blockIdx.z;
    const int seg0 = g_seg_start[r];
    const int cnt  = g_seg_start[r + 1] - seg0;
    const int m0   = blockIdx.x * 128;         // TRANSPOSED: x = m-tile (fastest)
    if (m0 >= cnt) return;
    const int n0 = blockIdx.y * 128;           // TRANSPOSED: y = n-tile

    const float* B    = Bbase + (size_t)r * (size_t)KTOT * NTOT;
    const float* bias = biasBase + (size_t)r * NTOT;

    const int tid  = threadIdx.x;
    const int warp = tid >> 5;
    const int lane = tid & 31;
    const int wm = warp & 1;    // 2 warp-rows of 64
    const int wn = warp >> 1;   // 2 warp-cols of 64
    const int lg = lane >> 2;
    const int lt = lane & 3;

    // ---- A loader: 128x32 floats = 1024 16B chunks, 8 per thread, cp.async ----
    auto loadA = [&](int kt, int buf) {
        const int k0 = kt * BK;
        float* dA = sA + buf * TILE_FLOATS;
        #pragma unroll
        for (int i = 0; i < 8; i++) {
            int idx = tid + i * 128;
            int row = idx >> 3;
            int ch  = idx & 7;
            int grow = seg0 + m0 + row;
            if (grow > TOK - 1) grow = TOK - 1;     // clamp; stores guarded
            cp16(smem_u32(dA + row * TSTRIDE + ch * 4),
                 Abase + (size_t)grow * KTOT + k0 + ch * 4);
        }
        asm volatile("cp.async.commit_group;\n");
    };

    // ---- B staging: thread tid owns column n = n0+tid of the B tile ----
    const float* bCol = B + n0 + tid;            // + k*NTOT indexes rows
    float rawB[BK];                              // raw fp32 column for tile kt
    auto ldgB = [&](int kt) {
        const int k0 = kt * BK;
        #pragma unroll
        for (int j = 0; j < BK; j++)
            rawB[j] = __ldg(bCol + (size_t)(k0 + j) * NTOT);
    };
    auto stsB = [&](int buf) {                   // round + store row n=tid of sBt
        float* dst = sBt + buf * TILE_FLOATS + tid * TSTRIDE;
        #pragma unroll
        for (int j = 0; j < BK; j += 4) {
            float4 v;
            v.x = round_tf32(rawB[j + 0]);
            v.y = round_tf32(rawB[j + 1]);
            v.z = round_tf32(rawB[j + 2]);
            v.w = round_tf32(rawB[j + 3]);
            *reinterpret_cast<float4*>(dst + j) = v;
        }
    };

    float acc[4][8][4];
    #pragma unroll
    for (int mt = 0; mt < 4; mt++)
        #pragma unroll
        for (int nt = 0; nt < 8; nt++)
            #pragma unroll
            for (int j = 0; j < 4; j++) acc[mt][nt][j] = 0.f;

    // ldmatrix lane addresses (bytes within a tile buffer) — proven mappings
    const int a_row = wm * 64 + (lane & 7) + (((lane >> 3) & 1) << 3);
    const int a_colb = (((lane >> 4) & 1) << 4);
    const uint32_t aBase = smem_u32(sA) + (uint32_t)(a_row * TSTRIDE * 4 + a_colb);
    const int b_row = wn * 64 + (lane & 7) + (((lane >> 4) & 1) << 3);
    const int b_colb = (((lane >> 3) & 1) << 4);
    const uint32_t bBase = smem_u32(sBt) + (uint32_t)(b_row * TSTRIDE * 4 + b_colb);

    // one ks step of fragment loads + MMAs (R10/R13 verbatim)
    auto do_ks = [&](uint32_t aBuf, uint32_t bBuf, int ks) {
        uint32_t afr[4][4];
        #pragma unroll
        for (int mt = 0; mt < 4; mt++)
            ldsm4(afr[mt], aBuf + mt * (16 * TSTRIDE * 4) + ks * 32);

        uint32_t bfr[8][2];
        #pragma unroll
        for (int ntp = 0; ntp < 4; ntp++) {
            uint32_t q[4];
            ldsm4(q, bBuf + ntp * (16 * TSTRIDE * 4) + ks * 32);
            bfr[2 * ntp + 0][0] = q[0];
            bfr[2 * ntp + 0][1] = q[1];
            bfr[2 * ntp + 1][0] = q[2];
            bfr[2 * ntp + 1][1] = q[3];
        }
        #pragma unroll
        for (int mt = 0; mt < 4; mt++)
            #pragma unroll
            for (int nt = 0; nt < 8; nt++)
                mma_tf32(acc[mt][nt], afr[mt], bfr[nt]);
    };

    // ---- prologue ----
    loadA(0, 0);                 // group: A0
    loadA(1, 1);                 // group: A1
    ldgB(0);
    stsB(0);                     // sBt[0] = B(0); no readers yet
    if (NK > 1) ldgB(1);         // rawB = B(1)

    for (int kt = 0; kt < NK; kt++) {
        const int abuf = kt % ASTAGES;
        const int bbuf = kt & 1;
        // A(kt) complete for this thread (pending = {kt, kt+1} before wait)
        asm volatile("cp.async.wait_group 1;\n");
        // ...for all threads; STS of sBt[bbuf] visible; stage buffers from kt-1 free
        __syncthreads();

        const uint32_t aBuf = aBase + abuf * (TILE_FLOATS * 4);
        const uint32_t bBuf = bBase + bbuf * (TILE_FLOATS * 4);
        const bool more  = kt + 1 < NK;
        const bool more2 = kt + 2 < NK;

        // R13-proven staging placement: g0=loadA, g1=stsB, g2=ldgB
        do_ks(aBuf, bBuf, 0);
        if (more2) loadA(kt + 2, (kt + 2) % ASTAGES);    // g0: commit A(kt+2)
        else       asm volatile("cp.async.commit_group;\n");  // keep accounting exact
        do_ks(aBuf, bBuf, 1);
        if (more) stsB(bbuf ^ 1);                        // g1: sBt[(kt+1)&1] = B(kt+1)
        do_ks(aBuf, bBuf, 2);
        if (more2) ldgB(kt + 2);                         // g2: rawB = B(kt+2), max dist
        do_ks(aBuf, bBuf, 3);
    }

    __syncthreads();

    // epilogue: bias (+relu+tf32-round for phase1), guarded float2 stores
    #pragma unroll
    for (int mt = 0; mt < 4; mt++) {
        #pragma unroll
        for (int half = 0; half < 2; half++) {
            const int rowl = wm * 64 + mt * 16 + lg + half * 8;
            const int mrow = m0 + rowl;
            if (mrow < cnt) {
                float* crow = Cbase + (size_t)(seg0 + mrow) * NTOT;
                #pragma unroll
                for (int nt = 0; nt < 8; nt++) {
                    const int col = n0 + wn * 64 + nt * 8 + lt * 2;
                    float v0 = acc[mt][nt][half * 2 + 0] + bias[col];
                    float v1 = acc[mt][nt][half * 2 + 1] + bias[col + 1];
                    if (RELU) {
                        v0 = round_tf32(fmaxf(v0, 0.f));
                        v1 = round_tf32(fmaxf(v1, 0.f));
                    }
                    *reinterpret_cast<float2*>(crow + col) = make_float2(v0, v1);
                }
            }
        }
    }
}

// ---------------- softmax + scatter: 512 threads, float4, fast exp ----------------
__global__ __launch_bounds__(512)
void softmax_kernel(float* __restrict__ out) {
    const int i   = blockIdx.x;
    const int tok = g_perm[i];
    const float4* lrow = reinterpret_cast<const float4*>(g_logits + (size_t)i * VDIM);
    float4*       orow = reinterpret_cast<float4*>(out + (size_t)tok * VDIM);
    const int tid = threadIdx.x;

    float4 v = lrow[tid];               // 512 threads x 4 = 2048
    float mx = fmaxf(fmaxf(v.x, v.y), fmaxf(v.z, v.w));
    #pragma unroll
    for (int o = 16; o; o >>= 1) mx = fmaxf(mx, __shfl_xor_sync(0xffffffffu, mx, o));

    __shared__ float sred[16];
    const int w = tid >> 5;
    if ((tid & 31) == 0) sred[w] = mx;
    __syncthreads();
    float bmx = sred[0];
    #pragma unroll
    for (int j = 1; j < 16; j++) bmx = fmaxf(bmx, sred[j]);

    v.x = __expf(v.x - bmx);
    v.y = __expf(v.y - bmx);
    v.z = __expf(v.z - bmx);
    v.w = __expf(v.w - bmx);
    float s = (v.x + v.y) + (v.z + v.w);
    #pragma unroll
    for (int o = 16; o; o >>= 1) s += __shfl_xor_sync(0xffffffffu, s, o);
    __syncthreads();
    if ((tid & 31) == 0) sred[w] = s;
    __syncthreads();
    float tot = 0.f;
    #pragma unroll
    for (int j = 0; j < 16; j++) tot += sred[j];
    const float inv = 1.f / tot;
    v.x *= inv; v.y *= inv; v.z *= inv; v.w *= inv;
    orow[tid] = v;
}

// ---------------- launch ----------------
extern "C" void kernel_launch(void* const* d_in, const int* in_sizes, int n_in,
                              void* d_out, int out_size) {
    const float* e_two     = (const float*)d_in[0];   // [4,1024,768]
    const int*   route_ids = (const int*)d_in[1];     // [4,1024]
    const float* W1        = (const float*)d_in[2];   // [8,768,3072]
    const float* b1        = (const float*)d_in[3];   // [8,3072]
    const float* W2        = (const float*)d_in[4];   // [8,3072,2048]
    const float* b2        = (const float*)d_in[5];   // [8,2048]
    float*       out       = (float*)d_out;           // [4,1024,2048]

    void *pA, *pH, *pL;
    cudaGetSymbolAddress(&pA, g_Aperm);
    cudaGetSymbolAddress(&pH, g_H);
    cudaGetSymbolAddress(&pL, g_logits);

    static bool attr_done = false;
    if (!attr_done) {
        cudaFuncSetAttribute(gemm_dlt<DDIM, FDIM, true>,
                             cudaFuncAttributeMaxDynamicSharedMemorySize, SMEM_BYTES);
        cudaFuncSetAttribute(gemm_dlt<FDIM, VDIM, false>,
                             cudaFuncAttributeMaxDynamicSharedMemorySize, SMEM_BYTES);
        attr_done = true;
    }

    bucket_kernel<<<1, 1024>>>(route_ids);
    gather_kernel<<<TOK, 192>>>(e_two);

    // TRANSPOSED grids: x = m-tiles (fastest), y = n-tiles
    dim3 g1(TOK / 128, FDIM / 128, RNUM);   // (32, 24, 8)
    gemm_dlt<DDIM, FDIM, true><<<g1, 128, SMEM_BYTES>>>(
        (const float*)pA, W1, b1, (float*)pH);

    dim3 g2(TOK / 128, VDIM / 128, RNUM);   // (32, 16, 8)
    gemm_dlt<FDIM, VDIM, false><<<g2, 128, SMEM_BYTES>>>(
        (const float*)pH, W2, b2, (float*)pL);

    softmax_kernel<<<TOK, 512>>>(out);
}